// round 8
// baseline (speedup 1.0000x reference)
#include <cuda_runtime.h>
#include <cuda_fp16.h>
#include <cstdint>

// ---------------------------------------------------------------------------
// HierarchUpdateMlp — fp16 mma.sync (m16n8k16), K-stage 64, 1 sync/stage.
//   L1 (MODE1): m16-per-warp layout, warp-private A convert (syncwarp only)
//   L2/L3 (MODE0): m32n64 layout, single-sync double buffer
// fp16 smem tiles: 128 rows x 64 halfs (128B rows), chunk pos = j ^ (row&7).
// ---------------------------------------------------------------------------

#define NROWS_MAX 50176   // 392 tiles of 128 (N = 50000)

__device__ __align__(16) __half g_W1_0h[128 * 1280];
__device__ __align__(16) __half g_W1h[6 * 128 * 512];
__device__ __align__(16) __half g_W2h[6 * 128 * 256];
__device__ __align__(16) __half g_Wfh[256 * 768];
__device__ __align__(16) __half g_out1h[(size_t)NROWS_MAX * 896];
__device__ __align__(16) __half g_out2h[(size_t)NROWS_MAX * 768];

__constant__ int c_jA[7] = {0, 5, 7, 8, 11, 13, 14};
__constant__ int c_jB[7] = {0, 6, 9, 10, 12, 15, 16};
__constant__ int c_pA[6] = {0, 1, 1, 1, 4, 4};
__constant__ int c_pB[6] = {1, 2, 3, 4, 5, 6};

// smem (bytes):
//  MODE1 (l1): [0,65536) fp32 staging x2, [65536,81920) hA (1 buf),
//              [81920,114688) hB x2
//  MODE0:      [0,32768) hA x2, [32768,65536) hB x2
#define SMEM_L1 114688
#define SMEM_L23 65536

__device__ __forceinline__ unsigned smem_u32(const void* p) {
    return (unsigned)__cvta_generic_to_shared(p);
}

__device__ __forceinline__ void ldsm4(unsigned addr, unsigned& r0, unsigned& r1,
                                      unsigned& r2, unsigned& r3) {
    asm volatile("ldmatrix.sync.aligned.m8n8.x4.shared.b16 {%0,%1,%2,%3}, [%4];"
                 : "=r"(r0), "=r"(r1), "=r"(r2), "=r"(r3)
                 : "r"(addr));
}

__device__ __forceinline__ void mma_f16(float* c, const unsigned* a, const unsigned* b) {
    asm volatile(
        "mma.sync.aligned.m16n8k16.row.col.f32.f16.f16.f32 "
        "{%0,%1,%2,%3}, {%4,%5,%6,%7}, {%8,%9}, {%0,%1,%2,%3};"
        : "+f"(c[0]), "+f"(c[1]), "+f"(c[2]), "+f"(c[3])
        : "r"(a[0]), "r"(a[1]), "r"(a[2]), "r"(a[3]), "r"(b[0]), "r"(b[1]));
}

// Generic 128(M)x128(N) GEMM, K streamed in 64-col stages (K compile-time).
// A gathered from up to 2 contiguous col blocks (col = k<blk ? offA0+k : offA1+k-blk).
// MODE==1: A fp32 via double-buffered fp32 staging + warp-private smem convert;
//          warp tile m16 x n128.
// MODE==0: A fp16; warp tile m32 x n64.
template <int MODE, bool HALF_OUT, int K>
__device__ __forceinline__ void gemm16(
    const void* __restrict__ Av, int lda, int offA0, int offA1, int blk,
    const __half* __restrict__ B, int ldb,
    const float* __restrict__ bias,
    void* __restrict__ Cv, int ldc,
    int nrows)
{
    extern __shared__ char smc[];
    float*  stg = reinterpret_cast<float*>(smc);                        // MODE1: 2 bufs
    __half* hA  = reinterpret_cast<__half*>(smc + (MODE ? 65536 : 0));
    __half* hB  = hA + (MODE ? 8192 : 16384);

    const int tid   = threadIdx.x;
    const int lane  = tid & 31;
    const int wid   = tid >> 5;
    const int tile  = blockIdx.x * 128;
    constexpr int KT = K >> 6;      // 64-K stages
    constexpr int MF = MODE ? 1 : 2;
    constexpr int NF = MODE ? 16 : 8;
    const int mbase = MODE ? wid * 16 : (wid & 3) * 32;
    const int nbase = MODE ? 0 : (wid >> 2) * 64;

    float acc[MF][NF][4];
#pragma unroll
    for (int i = 0; i < MF; i++)
#pragma unroll
        for (int j = 0; j < NF; j++)
#pragma unroll
            for (int q = 0; q < 4; q++) acc[i][j][q] = 0.f;

    const int rowIn = (lane & 7) + ((lane >> 3) & 1) * 8;
    const int hi    = (lane >> 4) & 1;

    // ---------- fill geometry ----------
    const int fr8  = tid >> 3;          // rows, stride 32 per i (B / A0 fills)
    const int fj   = tid & 7;
    const int fr16 = tid >> 4;          // rows, stride 16 per i (staging fill)
    const int fj16 = tid & 15;

    const __half* bSrc0 = B + (long)fr8 * ldb + fj * 8;
    unsigned bDst[4];
#pragma unroll
    for (int i = 0; i < 4; ++i) {
        int r = fr8 + i * 32;
        bDst[i] = smem_u32(hB + r * 64 + 8 * (fj ^ (r & 7)));
    }
    auto fillB = [&](int kt) {
        const unsigned boff = (unsigned)((kt & 1) * 16384);   // bytes
        const __half* src = bSrc0 + (kt << 6);
#pragma unroll
        for (int i = 0; i < 4; ++i)
            asm volatile("cp.async.cg.shared.global [%0], [%1], 16;"
                         ::"r"(bDst[i] + boff), "l"(src + (long)i * 32 * ldb));
    };

    const __half* a0Src[4];
    unsigned a0Dst[4];
    if (MODE == 0) {
#pragma unroll
        for (int i = 0; i < 4; ++i) {
            int r = fr8 + i * 32;
            int row = tile + r; if (row >= nrows) row = nrows - 1;
            a0Src[i] = (const __half*)Av + (long)row * lda;
            a0Dst[i] = smem_u32(hA + r * 64 + 8 * (fj ^ (r & 7)));
        }
    }
    auto fillA0 = [&](int kt) {
        const unsigned boff = (unsigned)((kt & 1) * 16384);
        int k   = (kt << 6) + fj * 8;
        int col = (k < blk) ? (offA0 + k) : (offA1 + (k - blk));
#pragma unroll
        for (int i = 0; i < 4; ++i)
            asm volatile("cp.async.cg.shared.global [%0], [%1], 16;"
                         ::"r"(a0Dst[i] + boff), "l"(a0Src[i] + col));
    };

    const float* a1Src[8];
    unsigned a1Dst[8];
    if (MODE == 1) {
#pragma unroll
        for (int i = 0; i < 8; ++i) {
            int r = fr16 + i * 16;
            int row = tile + r; if (row >= nrows) row = nrows - 1;
            a1Src[i] = (const float*)Av + (long)row * lda;
            a1Dst[i] = smem_u32(stg + r * 64 +
                                4 * ((fj16 & 8) | ((fj16 & 7) ^ (r & 7))));
        }
    }
    auto fillA1 = [&](int kt) {
        const unsigned boff = (unsigned)((kt & 1) * 32768);   // bytes (stg buf)
        int k   = (kt << 6) + fj16 * 4;
        int col = (k < blk) ? (offA0 + k) : (offA1 + (k - blk));
#pragma unroll
        for (int i = 0; i < 8; ++i)
            asm volatile("cp.async.cg.shared.global [%0], [%1], 16;"
                         ::"r"(a1Dst[i] + boff), "l"(a1Src[i] + col));
    };

    // warp-private convert: warp wid owns rows wid*16 .. wid*16+15
    auto convertA = [&](int buf) {
        const float* fs = stg + buf * 8192;
        const int r  = wid * 16 + (lane >> 1);
        const int h  = lane & 1;
        const int rx = r & 7;
#pragma unroll
        for (int q = 0; q < 4; ++q) {
            float4 va = *reinterpret_cast<const float4*>(
                fs + r * 64 + 4 * (h * 8 + ((2 * q) ^ rx)));
            float4 vb = *reinterpret_cast<const float4*>(
                fs + r * 64 + 4 * (h * 8 + ((2 * q + 1) ^ rx)));
            __half2 h0 = __floats2half2_rn(va.x, va.y);
            __half2 h1 = __floats2half2_rn(va.z, va.w);
            __half2 h2 = __floats2half2_rn(vb.x, vb.y);
            __half2 h3 = __floats2half2_rn(vb.z, vb.w);
            uint4 u;
            u.x = *reinterpret_cast<unsigned*>(&h0);
            u.y = *reinterpret_cast<unsigned*>(&h1);
            u.z = *reinterpret_cast<unsigned*>(&h2);
            u.w = *reinterpret_cast<unsigned*>(&h3);
            *reinterpret_cast<uint4*>(hA + r * 64 + 8 * ((h * 4 + q) ^ rx)) = u;
        }
    };

    auto compute_stage = [&](int buf) {
        const __half* As = MODE ? hA : hA + buf * 8192;
        const __half* Bs = hB + buf * 8192;
#pragma unroll
        for (int s = 0; s < 4; ++s) {         // four k16 steps per 64-K stage
            const int j = 2 * s + hi;
            unsigned a[MF][4];
#pragma unroll
            for (int mf = 0; mf < MF; ++mf) {
                int row = mbase + mf * 16 + rowIn;
                ldsm4(smem_u32(As + row * 64 + 8 * (j ^ (row & 7))),
                      a[mf][0], a[mf][1], a[mf][2], a[mf][3]);
            }
#pragma unroll
            for (int nh = 0; nh < NF / 8; ++nh) {
                unsigned b[8][2];
#pragma unroll
                for (int nq = 0; nq < 4; ++nq) {
                    int nrow = nbase + nh * 64 + nq * 16 + rowIn;
                    unsigned r0, r1, r2, r3;
                    ldsm4(smem_u32(Bs + nrow * 64 + 8 * (j ^ (nrow & 7))),
                          r0, r1, r2, r3);
                    b[nq * 2][0]     = r0;
                    b[nq * 2 + 1][0] = r1;
                    b[nq * 2][1]     = r2;
                    b[nq * 2 + 1][1] = r3;
                }
#pragma unroll
                for (int mf = 0; mf < MF; ++mf)
#pragma unroll
                    for (int nf = 0; nf < 8; ++nf)
                        mma_f16(acc[mf][nh * 8 + nf], a[mf], b[nf]);
            }
        }
    };

    if (MODE == 1) {
        fillA1(0); fillB(0);
        asm volatile("cp.async.commit_group;");
#pragma unroll 4
        for (int kt = 0; kt < KT; ++kt) {
            asm volatile("cp.async.wait_group 0;" ::: "memory");
            __syncthreads();        // stage kt landed; all warps done stage kt-1
            if (kt + 1 < KT) {
                fillA1(kt + 1); fillB(kt + 1);
                asm volatile("cp.async.commit_group;");
            }
            convertA(kt & 1);       // warp-private rows
            __syncwarp();
            compute_stage(kt & 1);
        }
    } else {
        fillA0(0); fillB(0);
        asm volatile("cp.async.commit_group;");
#pragma unroll 4
        for (int kt = 0; kt < KT; ++kt) {
            asm volatile("cp.async.wait_group 0;" ::: "memory");
            __syncthreads();        // stage kt landed; all warps done stage kt-1
            if (kt + 1 < KT) {
                fillA0(kt + 1); fillB(kt + 1);
                asm volatile("cp.async.commit_group;");
            }
            compute_stage(kt & 1);
        }
    }

    // Epilogue: bias + relu; store fp16 (intermediates) or fp32 (final)
    const int rbase = tile + mbase + (lane >> 2);
#pragma unroll
    for (int mf = 0; mf < MF; ++mf) {
        int r0 = rbase + mf * 16;
#pragma unroll
        for (int nf = 0; nf < NF; ++nf) {
            int col  = nbase + nf * 8 + (lane & 3) * 2;
            float b0 = __ldg(bias + col);
            float b1 = __ldg(bias + col + 1);
            float v0 = fmaxf(acc[mf][nf][0] + b0, 0.f);
            float v1 = fmaxf(acc[mf][nf][1] + b1, 0.f);
            float v2 = fmaxf(acc[mf][nf][2] + b0, 0.f);
            float v3 = fmaxf(acc[mf][nf][3] + b1, 0.f);
            if (HALF_OUT) {
                __half* Ch = (__half*)Cv;
                if (r0 < nrows)
                    *reinterpret_cast<__half2*>(Ch + (long)r0 * ldc + col) =
                        __floats2half2_rn(v0, v1);
                if (r0 + 8 < nrows)
                    *reinterpret_cast<__half2*>(Ch + (long)(r0 + 8) * ldc + col) =
                        __floats2half2_rn(v2, v3);
            } else {
                float* Cf = (float*)Cv;
                if (r0 < nrows)
                    *reinterpret_cast<float2*>(Cf + (long)r0 * ldc + col) =
                        make_float2(v0, v1);
                if (r0 + 8 < nrows)
                    *reinterpret_cast<float2*>(Cf + (long)(r0 + 8) * ldc + col) =
                        make_float2(v2, v3);
            }
        }
    }
}

// ---------------- kernels ----------------

__global__ void prep_kernel(const float* __restrict__ w10, const float* __restrict__ w1,
                            const float* __restrict__ w2, const float* __restrict__ wf) {
    int i      = blockIdx.x * blockDim.x + threadIdx.x;
    int stride = gridDim.x * blockDim.x;
    for (int j = i; j < 128 * 1280; j += stride) g_W1_0h[j] = __float2half_rn(w10[j]);
    for (int j = i; j < 6 * 128 * 512; j += stride) g_W1h[j] = __float2half_rn(w1[j]);
    for (int j = i; j < 6 * 128 * 256; j += stride) g_W2h[j] = __float2half_rn(w2[j]);
    for (int j = i; j < 256 * 768; j += stride) g_Wfh[j] = __float2half_rn(wf[j]);
}

__global__ void __launch_bounds__(256, 2)
l1_kernel(const float* __restrict__ update, const float* __restrict__ b1_0,
          const float* __restrict__ b1, int nrows) {
    int g = blockIdx.y;
    if (g == 0) {
        gemm16<1, true, 1280>(update, 4352, 0, 0, 1 << 20,
                              g_W1_0h, 1280, b1_0, g_out1h, 896, nrows);
    } else {
        gemm16<1, true, 512>(update, 4352, c_jA[g] * 256, c_jB[g] * 256, 256,
                             g_W1h + (g - 1) * 128 * 512, 512, b1 + (g - 1) * 128,
                             g_out1h + g * 128, 896, nrows);
    }
}

__global__ void __launch_bounds__(256, 2)
l2_kernel(const float* __restrict__ b2, int nrows) {
    int g = blockIdx.y;
    gemm16<0, true, 256>(g_out1h, 896, c_pA[g] * 128, c_pB[g] * 128, 128,
                         g_W2h + g * 128 * 256, 256, b2 + g * 128,
                         g_out2h + g * 128, 768, nrows);
}

__global__ void __launch_bounds__(256, 2)
l3_kernel(const float* __restrict__ bf, float* __restrict__ out, int nrows) {
    int y = blockIdx.y;   // output column half
    gemm16<0, false, 768>(g_out2h, 768, 0, 0, 1 << 20,
                          g_Wfh + y * 128 * 768, 768, bf + y * 128,
                          out + y * 128, 256, nrows);
}

// ---------------- launch ----------------

extern "C" void kernel_launch(void* const* d_in, const int* in_sizes, int n_in,
                              void* d_out, int out_size) {
    const float* update = (const float*)d_in[0];
    const float* W1_0   = (const float*)d_in[1];
    const float* b1_0   = (const float*)d_in[2];
    const float* W1     = (const float*)d_in[3];
    const float* b1     = (const float*)d_in[4];
    const float* W2     = (const float*)d_in[5];
    const float* b2     = (const float*)d_in[6];
    const float* Wf     = (const float*)d_in[7];
    const float* bf     = (const float*)d_in[8];

    int N  = in_sizes[0] / (17 * 256);
    int MT = (N + 127) / 128;

    cudaFuncSetAttribute(l1_kernel, cudaFuncAttributeMaxDynamicSharedMemorySize, SMEM_L1);
    cudaFuncSetAttribute(l2_kernel, cudaFuncAttributeMaxDynamicSharedMemorySize, SMEM_L23);
    cudaFuncSetAttribute(l3_kernel, cudaFuncAttributeMaxDynamicSharedMemorySize, SMEM_L23);

    prep_kernel<<<232, 256>>>(W1_0, W1, W2, Wf);
    l1_kernel<<<dim3(MT, 7), 256, SMEM_L1>>>(update, b1_0, b1, N);
    l2_kernel<<<dim3(MT, 6), 256, SMEM_L23>>>(b2, N);
    l3_kernel<<<dim3(MT, 2), 256, SMEM_L23>>>(bf, (float*)d_out, N);
}

// round 9
// speedup vs baseline: 1.0294x; 1.0294x over previous
#include <cuda_runtime.h>
#include <cuda_fp16.h>
#include <cstdint>

// ---------------------------------------------------------------------------
// HierarchUpdateMlp — fp16 mma.sync (m16n8k16), K-stage 64.
//   All layers: m32n64 warp tile (4x2 warps), 128x128 block tile.
//   MODE1 (l1): fp32 A via double-buffered staging, block convert, 2 syncs/stage,
//               fill issued before convert (overlaps convert+compute).
//   MODE0 (l2/l3): fp16 A, 1 sync/stage.
// fp16 smem tiles: 128 rows x 64 halfs (128B rows), chunk pos = j ^ (row&7).
// ---------------------------------------------------------------------------

#define NROWS_MAX 50176   // 392 tiles of 128 (N = 50000)

__device__ __align__(16) __half g_W1_0h[128 * 1280];
__device__ __align__(16) __half g_W1h[6 * 128 * 512];
__device__ __align__(16) __half g_W2h[6 * 128 * 256];
__device__ __align__(16) __half g_Wfh[256 * 768];
__device__ __align__(16) __half g_out1h[(size_t)NROWS_MAX * 896];
__device__ __align__(16) __half g_out2h[(size_t)NROWS_MAX * 768];

__constant__ int c_jA[7] = {0, 5, 7, 8, 11, 13, 14};
__constant__ int c_jB[7] = {0, 6, 9, 10, 12, 15, 16};
__constant__ int c_pA[6] = {0, 1, 1, 1, 4, 4};
__constant__ int c_pB[6] = {1, 2, 3, 4, 5, 6};

// smem (bytes):
//  MODE1 (l1): [0,65536) fp32 staging x2, [65536,81920) hA (1 buf),
//              [81920,114688) hB x2
//  MODE0:      [0,32768) hA x2, [32768,65536) hB x2
#define SMEM_L1 114688
#define SMEM_L23 65536

__device__ __forceinline__ unsigned smem_u32(const void* p) {
    return (unsigned)__cvta_generic_to_shared(p);
}

__device__ __forceinline__ void ldsm4(unsigned addr, unsigned& r0, unsigned& r1,
                                      unsigned& r2, unsigned& r3) {
    asm volatile("ldmatrix.sync.aligned.m8n8.x4.shared.b16 {%0,%1,%2,%3}, [%4];"
                 : "=r"(r0), "=r"(r1), "=r"(r2), "=r"(r3)
                 : "r"(addr));
}

__device__ __forceinline__ void mma_f16(float* c, const unsigned* a, const unsigned* b) {
    asm volatile(
        "mma.sync.aligned.m16n8k16.row.col.f32.f16.f16.f32 "
        "{%0,%1,%2,%3}, {%4,%5,%6,%7}, {%8,%9}, {%0,%1,%2,%3};"
        : "+f"(c[0]), "+f"(c[1]), "+f"(c[2]), "+f"(c[3])
        : "r"(a[0]), "r"(a[1]), "r"(a[2]), "r"(a[3]), "r"(b[0]), "r"(b[1]));
}

// Generic 128(M)x128(N) GEMM, K streamed in 64-col stages (K compile-time).
// A gathered from up to 2 contiguous col blocks (col = k<blk ? offA0+k : offA1+k-blk).
template <int MODE, bool HALF_OUT, int K>
__device__ __forceinline__ void gemm16(
    const void* __restrict__ Av, int lda, int offA0, int offA1, int blk,
    const __half* __restrict__ B, int ldb,
    const float* __restrict__ bias,
    void* __restrict__ Cv, int ldc,
    int nrows)
{
    extern __shared__ char smc[];
    float*  stg = reinterpret_cast<float*>(smc);                        // MODE1: 2 bufs
    __half* hA  = reinterpret_cast<__half*>(smc + (MODE ? 65536 : 0));
    __half* hB  = hA + (MODE ? 8192 : 16384);

    const int tid   = threadIdx.x;
    const int lane  = tid & 31;
    const int wid   = tid >> 5;
    const int warpM = wid & 3;      // 4 warps over M (32 rows)
    const int warpN = wid >> 2;     // 2 warps over N (64 cols)
    const int tile  = blockIdx.x * 128;
    constexpr int KT = K >> 6;      // 64-K stages

    float acc[2][8][4];
#pragma unroll
    for (int i = 0; i < 2; i++)
#pragma unroll
        for (int j = 0; j < 8; j++)
#pragma unroll
            for (int q = 0; q < 4; q++) acc[i][j][q] = 0.f;

    const int rowIn = (lane & 7) + ((lane >> 3) & 1) * 8;
    const int hi    = (lane >> 4) & 1;

    // ---------- fill geometry ----------
    const int fr8  = tid >> 3;          // rows, stride 32 per i (B / A0 fills)
    const int fj   = tid & 7;
    const int fr16 = tid >> 4;          // rows, stride 16 per i (staging fill)
    const int fj16 = tid & 15;

    const __half* bSrc0 = B + (long)fr8 * ldb + fj * 8;
    unsigned bDst[4];
#pragma unroll
    for (int i = 0; i < 4; ++i) {
        int r = fr8 + i * 32;
        bDst[i] = smem_u32(hB + r * 64 + 8 * (fj ^ (r & 7)));
    }
    auto fillB = [&](int kt) {
        const unsigned boff = (unsigned)((kt & 1) * 16384);   // bytes
        const __half* src = bSrc0 + (kt << 6);
#pragma unroll
        for (int i = 0; i < 4; ++i)
            asm volatile("cp.async.cg.shared.global [%0], [%1], 16;"
                         ::"r"(bDst[i] + boff), "l"(src + (long)i * 32 * ldb));
    };

    const __half* a0Src[4];
    unsigned a0Dst[4];
    if (MODE == 0) {
#pragma unroll
        for (int i = 0; i < 4; ++i) {
            int r = fr8 + i * 32;
            int row = tile + r; if (row >= nrows) row = nrows - 1;
            a0Src[i] = (const __half*)Av + (long)row * lda;
            a0Dst[i] = smem_u32(hA + r * 64 + 8 * (fj ^ (r & 7)));
        }
    }
    auto fillA0 = [&](int kt) {
        const unsigned boff = (unsigned)((kt & 1) * 16384);
        int k   = (kt << 6) + fj * 8;
        int col = (k < blk) ? (offA0 + k) : (offA1 + (k - blk));
#pragma unroll
        for (int i = 0; i < 4; ++i)
            asm volatile("cp.async.cg.shared.global [%0], [%1], 16;"
                         ::"r"(a0Dst[i] + boff), "l"(a0Src[i] + col));
    };

    const float* a1Src[8];
    unsigned a1Dst[8];
    if (MODE == 1) {
#pragma unroll
        for (int i = 0; i < 8; ++i) {
            int r = fr16 + i * 16;
            int row = tile + r; if (row >= nrows) row = nrows - 1;
            a1Src[i] = (const float*)Av + (long)row * lda;
            a1Dst[i] = smem_u32(stg + r * 64 +
                                4 * ((fj16 & 8) | ((fj16 & 7) ^ (r & 7))));
        }
    }
    auto fillA1 = [&](int kt) {
        const unsigned boff = (unsigned)((kt & 1) * 32768);   // staging buf (bytes)
        int k   = (kt << 6) + fj16 * 4;
        int col = (k < blk) ? (offA0 + k) : (offA1 + (k - blk));
#pragma unroll
        for (int i = 0; i < 8; ++i)
            asm volatile("cp.async.cg.shared.global [%0], [%1], 16;"
                         ::"r"(a1Dst[i] + boff), "l"(a1Src[i] + col));
    };

    // block-wide convert: stg[buf] -> hA (thread: row tid>>1, half tid&1)
    auto convertA = [&](int buf) {
        const float* fs = stg + buf * 8192;
        const int r  = tid >> 1;
        const int h  = tid & 1;
        const int rx = r & 7;
#pragma unroll
        for (int q = 0; q < 4; ++q) {
            float4 va = *reinterpret_cast<const float4*>(
                fs + r * 64 + 4 * (h * 8 + ((2 * q) ^ rx)));
            float4 vb = *reinterpret_cast<const float4*>(
                fs + r * 64 + 4 * (h * 8 + ((2 * q + 1) ^ rx)));
            __half2 h0 = __floats2half2_rn(va.x, va.y);
            __half2 h1 = __floats2half2_rn(va.z, va.w);
            __half2 h2 = __floats2half2_rn(vb.x, vb.y);
            __half2 h3 = __floats2half2_rn(vb.z, vb.w);
            uint4 u;
            u.x = *reinterpret_cast<unsigned*>(&h0);
            u.y = *reinterpret_cast<unsigned*>(&h1);
            u.z = *reinterpret_cast<unsigned*>(&h2);
            u.w = *reinterpret_cast<unsigned*>(&h3);
            *reinterpret_cast<uint4*>(hA + r * 64 + 8 * ((h * 4 + q) ^ rx)) = u;
        }
    };

    auto compute_stage = [&](int buf) {
        const __half* As = MODE ? hA : hA + buf * 8192;
        const __half* Bs = hB + buf * 8192;
#pragma unroll
        for (int s = 0; s < 4; ++s) {         // four k16 steps per 64-K stage
            const int j = 2 * s + hi;
            unsigned a[2][4];
#pragma unroll
            for (int mf = 0; mf < 2; ++mf) {
                int row = warpM * 32 + mf * 16 + rowIn;
                ldsm4(smem_u32(As + row * 64 + 8 * (j ^ (row & 7))),
                      a[mf][0], a[mf][1], a[mf][2], a[mf][3]);
            }
            unsigned b[8][2];
#pragma unroll
            for (int nq = 0; nq < 4; ++nq) {
                int nrow = warpN * 64 + nq * 16 + rowIn;
                unsigned r0, r1, r2, r3;
                ldsm4(smem_u32(Bs + nrow * 64 + 8 * (j ^ (nrow & 7))),
                      r0, r1, r2, r3);
                b[nq * 2][0]     = r0;
                b[nq * 2 + 1][0] = r1;
                b[nq * 2][1]     = r2;
                b[nq * 2 + 1][1] = r3;
            }
#pragma unroll
            for (int mf = 0; mf < 2; ++mf)
#pragma unroll
                for (int nf = 0; nf < 8; ++nf)
                    mma_f16(acc[mf][nf], a[mf], b[nf]);
        }
    };

    if (MODE == 1) {
        fillA1(0); fillB(0);
        asm volatile("cp.async.commit_group;");
#pragma unroll 4
        for (int kt = 0; kt < KT; ++kt) {
            asm volatile("cp.async.wait_group 0;" ::: "memory");
            __syncthreads();        // fill(kt) landed; compute(kt-1) done;
                                    // stg[(kt+1)&1] free (convert(kt-1) finished)
            if (kt + 1 < KT) {
                fillA1(kt + 1); fillB(kt + 1);
                asm volatile("cp.async.commit_group;");
            }
            convertA(kt & 1);       // stg[kt&1] -> hA (overlapped by cp.async)
            __syncthreads();        // converts visible to all warps
            compute_stage(kt & 1);
        }
    } else {
        fillA0(0); fillB(0);
        asm volatile("cp.async.commit_group;");
#pragma unroll 4
        for (int kt = 0; kt < KT; ++kt) {
            asm volatile("cp.async.wait_group 0;" ::: "memory");
            __syncthreads();        // stage kt landed; all warps done stage kt-1
            if (kt + 1 < KT) {
                fillA0(kt + 1); fillB(kt + 1);
                asm volatile("cp.async.commit_group;");
            }
            compute_stage(kt & 1);
        }
    }

    // Epilogue: bias + relu; store fp16 (intermediates) or fp32 (final)
    const int rbase = tile + warpM * 32 + (lane >> 2);
#pragma unroll
    for (int mf = 0; mf < 2; ++mf) {
        int r0 = rbase + mf * 16;
#pragma unroll
        for (int nf = 0; nf < 8; ++nf) {
            int col  = warpN * 64 + nf * 8 + (lane & 3) * 2;
            float b0 = __ldg(bias + col);
            float b1 = __ldg(bias + col + 1);
            float v0 = fmaxf(acc[mf][nf][0] + b0, 0.f);
            float v1 = fmaxf(acc[mf][nf][1] + b1, 0.f);
            float v2 = fmaxf(acc[mf][nf][2] + b0, 0.f);
            float v3 = fmaxf(acc[mf][nf][3] + b1, 0.f);
            if (HALF_OUT) {
                __half* Ch = (__half*)Cv;
                if (r0 < nrows)
                    *reinterpret_cast<__half2*>(Ch + (long)r0 * ldc + col) =
                        __floats2half2_rn(v0, v1);
                if (r0 + 8 < nrows)
                    *reinterpret_cast<__half2*>(Ch + (long)(r0 + 8) * ldc + col) =
                        __floats2half2_rn(v2, v3);
            } else {
                float* Cf = (float*)Cv;
                if (r0 < nrows)
                    *reinterpret_cast<float2*>(Cf + (long)r0 * ldc + col) =
                        make_float2(v0, v1);
                if (r0 + 8 < nrows)
                    *reinterpret_cast<float2*>(Cf + (long)(r0 + 8) * ldc + col) =
                        make_float2(v2, v3);
            }
        }
    }
}

// ---------------- kernels ----------------

__global__ void prep_kernel(const float* __restrict__ w10, const float* __restrict__ w1,
                            const float* __restrict__ w2, const float* __restrict__ wf) {
    int i      = blockIdx.x * blockDim.x + threadIdx.x;
    int stride = gridDim.x * blockDim.x;
    for (int j = i; j < 128 * 1280; j += stride) g_W1_0h[j] = __float2half_rn(w10[j]);
    for (int j = i; j < 6 * 128 * 512; j += stride) g_W1h[j] = __float2half_rn(w1[j]);
    for (int j = i; j < 6 * 128 * 256; j += stride) g_W2h[j] = __float2half_rn(w2[j]);
    for (int j = i; j < 256 * 768; j += stride) g_Wfh[j] = __float2half_rn(wf[j]);
}

__global__ void __launch_bounds__(256, 2)
l1_kernel(const float* __restrict__ update, const float* __restrict__ b1_0,
          const float* __restrict__ b1, int nrows) {
    int g = blockIdx.y;
    if (g == 0) {
        gemm16<1, true, 1280>(update, 4352, 0, 0, 1 << 20,
                              g_W1_0h, 1280, b1_0, g_out1h, 896, nrows);
    } else {
        gemm16<1, true, 512>(update, 4352, c_jA[g] * 256, c_jB[g] * 256, 256,
                             g_W1h + (g - 1) * 128 * 512, 512, b1 + (g - 1) * 128,
                             g_out1h + g * 128, 896, nrows);
    }
}

__global__ void __launch_bounds__(256, 2)
l2_kernel(const float* __restrict__ b2, int nrows) {
    int g = blockIdx.y;
    gemm16<0, true, 256>(g_out1h, 896, c_pA[g] * 128, c_pB[g] * 128, 128,
                         g_W2h + g * 128 * 256, 256, b2 + g * 128,
                         g_out2h + g * 128, 768, nrows);
}

__global__ void __launch_bounds__(256, 2)
l3_kernel(const float* __restrict__ bf, float* __restrict__ out, int nrows) {
    int y = blockIdx.y;   // output column half
    gemm16<0, false, 768>(g_out2h, 768, 0, 0, 1 << 20,
                          g_Wfh + y * 128 * 768, 768, bf + y * 128,
                          out + y * 128, 256, nrows);
}

// ---------------- launch ----------------

extern "C" void kernel_launch(void* const* d_in, const int* in_sizes, int n_in,
                              void* d_out, int out_size) {
    const float* update = (const float*)d_in[0];
    const float* W1_0   = (const float*)d_in[1];
    const float* b1_0   = (const float*)d_in[2];
    const float* W1     = (const float*)d_in[3];
    const float* b1     = (const float*)d_in[4];
    const float* W2     = (const float*)d_in[5];
    const float* b2     = (const float*)d_in[6];
    const float* Wf     = (const float*)d_in[7];
    const float* bf     = (const float*)d_in[8];

    int N  = in_sizes[0] / (17 * 256);
    int MT = (N + 127) / 128;

    cudaFuncSetAttribute(l1_kernel, cudaFuncAttributeMaxDynamicSharedMemorySize, SMEM_L1);
    cudaFuncSetAttribute(l2_kernel, cudaFuncAttributeMaxDynamicSharedMemorySize, SMEM_L23);
    cudaFuncSetAttribute(l3_kernel, cudaFuncAttributeMaxDynamicSharedMemorySize, SMEM_L23);

    prep_kernel<<<232, 256>>>(W1_0, W1, W2, Wf);
    l1_kernel<<<dim3(MT, 7), 256, SMEM_L1>>>(update, b1_0, b1, N);
    l2_kernel<<<dim3(MT, 6), 256, SMEM_L23>>>(b2, N);
    l3_kernel<<<dim3(MT, 2), 256, SMEM_L23>>>(bf, (float*)d_out, N);
}

// round 10
// speedup vs baseline: 1.0655x; 1.0351x over previous
#include <cuda_runtime.h>
#include <cuda_fp16.h>
#include <cstdint>

// ---------------------------------------------------------------------------
// HierarchUpdateMlp — fp16 mma.sync (m16n8k16), K-stage 64.
//   MODE1 (l1): R7-exact — fp32 staging (1 buf) + convert, hB x2, 80KB smem.
//   MODE0 (l2/l3): 3-stage ring, prefetch distance 2, 1 sync/stage, 96KB smem.
// fp16 smem tiles: 128 rows x 64 halfs (128B rows), chunk pos = j ^ (row&7).
// ---------------------------------------------------------------------------

#define NROWS_MAX 50176   // 392 tiles of 128 (N = 50000)

__device__ __align__(16) __half g_W1_0h[128 * 1280];
__device__ __align__(16) __half g_W1h[6 * 128 * 512];
__device__ __align__(16) __half g_W2h[6 * 128 * 256];
__device__ __align__(16) __half g_Wfh[256 * 768];
__device__ __align__(16) __half g_out1h[(size_t)NROWS_MAX * 896];
__device__ __align__(16) __half g_out2h[(size_t)NROWS_MAX * 768];

__constant__ int c_jA[7] = {0, 5, 7, 8, 11, 13, 14};
__constant__ int c_jB[7] = {0, 6, 9, 10, 12, 15, 16};
__constant__ int c_pA[6] = {0, 1, 1, 1, 4, 4};
__constant__ int c_pB[6] = {1, 2, 3, 4, 5, 6};

// smem (bytes):
//  MODE1 (l1): [0,32768) fp32 staging (1 buf), [32768,49152) hA (1 buf),
//              [49152,81920) hB x2
//  MODE0:      [0,49152) hA x3, [49152,98304) hB x3
#define SMEM_L1 81920
#define SMEM_L23 98304

__device__ __forceinline__ unsigned smem_u32(const void* p) {
    return (unsigned)__cvta_generic_to_shared(p);
}

__device__ __forceinline__ void ldsm4(unsigned addr, unsigned& r0, unsigned& r1,
                                      unsigned& r2, unsigned& r3) {
    asm volatile("ldmatrix.sync.aligned.m8n8.x4.shared.b16 {%0,%1,%2,%3}, [%4];"
                 : "=r"(r0), "=r"(r1), "=r"(r2), "=r"(r3)
                 : "r"(addr));
}

__device__ __forceinline__ void mma_f16(float* c, const unsigned* a, const unsigned* b) {
    asm volatile(
        "mma.sync.aligned.m16n8k16.row.col.f32.f16.f16.f32 "
        "{%0,%1,%2,%3}, {%4,%5,%6,%7}, {%8,%9}, {%0,%1,%2,%3};"
        : "+f"(c[0]), "+f"(c[1]), "+f"(c[2]), "+f"(c[3])
        : "r"(a[0]), "r"(a[1]), "r"(a[2]), "r"(a[3]), "r"(b[0]), "r"(b[1]));
}

// Generic 128(M)x128(N) GEMM, K streamed in 64-col stages (K compile-time).
// A gathered from up to 2 contiguous col blocks (col = k<blk ? offA0+k : offA1+k-blk).
template <int MODE, bool HALF_OUT, int K>
__device__ __forceinline__ void gemm16(
    const void* __restrict__ Av, int lda, int offA0, int offA1, int blk,
    const __half* __restrict__ B, int ldb,
    const float* __restrict__ bias,
    void* __restrict__ Cv, int ldc,
    int nrows)
{
    extern __shared__ char smc[];
    float*  stg = reinterpret_cast<float*>(smc);                        // MODE1 only
    __half* hA  = reinterpret_cast<__half*>(smc + (MODE ? 32768 : 0));
    __half* hB  = hA + (MODE ? 8192 : 24576);

    const int tid   = threadIdx.x;
    const int lane  = tid & 31;
    const int wid   = tid >> 5;
    const int warpM = wid & 3;      // 4 warps over M (32 rows)
    const int warpN = wid >> 2;     // 2 warps over N (64 cols)
    const int tile  = blockIdx.x * 128;
    constexpr int KT = K >> 6;      // 64-K stages

    float acc[2][8][4];
#pragma unroll
    for (int i = 0; i < 2; i++)
#pragma unroll
        for (int j = 0; j < 8; j++)
#pragma unroll
            for (int q = 0; q < 4; q++) acc[i][j][q] = 0.f;

    const int rowIn = (lane & 7) + ((lane >> 3) & 1) * 8;
    const int hi    = (lane >> 4) & 1;

    // ---------- fill geometry ----------
    const int fr8  = tid >> 3;          // rows, stride 32 per i (B / A0 fills)
    const int fj   = tid & 7;
    const int fr16 = tid >> 4;          // rows, stride 16 per i (staging fill)
    const int fj16 = tid & 15;

    const __half* bSrc0 = B + (long)fr8 * ldb + fj * 8;
    unsigned bDst[4];
#pragma unroll
    for (int i = 0; i < 4; ++i) {
        int r = fr8 + i * 32;
        bDst[i] = smem_u32(hB + r * 64 + 8 * (fj ^ (r & 7)));
    }
    // buf: stage buffer index (MODE1: kt&1; MODE0: kt%3)
    auto fillB = [&](int kt, int buf) {
        const unsigned boff = (unsigned)(buf * 16384);   // bytes
        const __half* src = bSrc0 + (kt << 6);
#pragma unroll
        for (int i = 0; i < 4; ++i)
            asm volatile("cp.async.cg.shared.global [%0], [%1], 16;"
                         ::"r"(bDst[i] + boff), "l"(src + (long)i * 32 * ldb));
    };

    const __half* a0Src[4];
    unsigned a0Dst[4];
    if (MODE == 0) {
#pragma unroll
        for (int i = 0; i < 4; ++i) {
            int r = fr8 + i * 32;
            int row = tile + r; if (row >= nrows) row = nrows - 1;
            a0Src[i] = (const __half*)Av + (long)row * lda;
            a0Dst[i] = smem_u32(hA + r * 64 + 8 * (fj ^ (r & 7)));
        }
    }
    auto fillA0 = [&](int kt, int buf) {
        const unsigned boff = (unsigned)(buf * 16384);
        int k   = (kt << 6) + fj * 8;
        int col = (k < blk) ? (offA0 + k) : (offA1 + (k - blk));
#pragma unroll
        for (int i = 0; i < 4; ++i)
            asm volatile("cp.async.cg.shared.global [%0], [%1], 16;"
                         ::"r"(a0Dst[i] + boff), "l"(a0Src[i] + col));
    };

    const float* a1Src[8];
    unsigned a1Dst[8];
    if (MODE == 1) {
#pragma unroll
        for (int i = 0; i < 8; ++i) {
            int r = fr16 + i * 16;
            int row = tile + r; if (row >= nrows) row = nrows - 1;
            a1Src[i] = (const float*)Av + (long)row * lda;
            a1Dst[i] = smem_u32(stg + r * 64 +
                                4 * ((fj16 & 8) | ((fj16 & 7) ^ (r & 7))));
        }
    }
    auto fillA1 = [&](int kt) {
        int k   = (kt << 6) + fj16 * 4;
        int col = (k < blk) ? (offA0 + k) : (offA1 + (k - blk));
#pragma unroll
        for (int i = 0; i < 8; ++i)
            asm volatile("cp.async.cg.shared.global [%0], [%1], 16;"
                         ::"r"(a1Dst[i]), "l"(a1Src[i] + col));
    };

    // staging -> hA fp16 convert (thread: row tid>>1, half tid&1)
    auto convertA = [&]() {
        const int r  = tid >> 1;
        const int h  = tid & 1;
        const int rx = r & 7;
#pragma unroll
        for (int q = 0; q < 4; ++q) {
            float4 va = *reinterpret_cast<const float4*>(
                stg + r * 64 + 4 * (h * 8 + ((2 * q) ^ rx)));
            float4 vb = *reinterpret_cast<const float4*>(
                stg + r * 64 + 4 * (h * 8 + ((2 * q + 1) ^ rx)));
            __half2 h0 = __floats2half2_rn(va.x, va.y);
            __half2 h1 = __floats2half2_rn(va.z, va.w);
            __half2 h2 = __floats2half2_rn(vb.x, vb.y);
            __half2 h3 = __floats2half2_rn(vb.z, vb.w);
            uint4 u;
            u.x = *reinterpret_cast<unsigned*>(&h0);
            u.y = *reinterpret_cast<unsigned*>(&h1);
            u.z = *reinterpret_cast<unsigned*>(&h2);
            u.w = *reinterpret_cast<unsigned*>(&h3);
            *reinterpret_cast<uint4*>(hA + r * 64 + 8 * ((h * 4 + q) ^ rx)) = u;
        }
    };

    auto compute_stage = [&](int buf) {
        const __half* As = MODE ? hA : hA + buf * 8192;
        const __half* Bs = hB + buf * 8192;
#pragma unroll
        for (int s = 0; s < 4; ++s) {         // four k16 steps per 64-K stage
            const int j = 2 * s + hi;
            unsigned a[2][4];
#pragma unroll
            for (int mf = 0; mf < 2; ++mf) {
                int row = warpM * 32 + mf * 16 + rowIn;
                ldsm4(smem_u32(As + row * 64 + 8 * (j ^ (row & 7))),
                      a[mf][0], a[mf][1], a[mf][2], a[mf][3]);
            }
            unsigned b[8][2];
#pragma unroll
            for (int nq = 0; nq < 4; ++nq) {
                int nrow = warpN * 64 + nq * 16 + rowIn;
                unsigned r0, r1, r2, r3;
                ldsm4(smem_u32(Bs + nrow * 64 + 8 * (j ^ (nrow & 7))),
                      r0, r1, r2, r3);
                b[nq * 2][0]     = r0;
                b[nq * 2 + 1][0] = r1;
                b[nq * 2][1]     = r2;
                b[nq * 2 + 1][1] = r3;
            }
#pragma unroll
            for (int mf = 0; mf < 2; ++mf)
#pragma unroll
                for (int nf = 0; nf < 8; ++nf)
                    mma_f16(acc[mf][nf], a[mf], b[nf]);
        }
    };

    if (MODE == 1) {
        // R7-exact loop: 2 syncs + convert per stage, hB double-buffered
        fillA1(0); fillB(0, 0);
        asm volatile("cp.async.commit_group;");
#pragma unroll 4
        for (int kt = 0; kt < KT; ++kt) {
            asm volatile("cp.async.wait_group 0;" ::: "memory");
            __syncthreads();                    // cp data visible; compute(kt-1) done
            convertA();                         // staging -> hA
            __syncthreads();                    // converts done; staging free
            if (kt + 1 < KT) {
                fillA1(kt + 1); fillB(kt + 1, (kt + 1) & 1);
                asm volatile("cp.async.commit_group;");
            }
            compute_stage(kt & 1);
        }
    } else {
        // 3-stage ring, prefetch distance 2, one sync per stage
        fillA0(0, 0); fillB(0, 0);
        asm volatile("cp.async.commit_group;");
        if (KT > 1) {
            fillA0(1, 1); fillB(1, 1);
            asm volatile("cp.async.commit_group;");
        }
        int buf = 0;
#pragma unroll 3
        for (int kt = 0; kt < KT; ++kt) {
            if (kt + 1 < KT) {
                asm volatile("cp.async.wait_group 1;" ::: "memory");   // fill(kt) landed
            } else {
                asm volatile("cp.async.wait_group 0;" ::: "memory");
            }
            __syncthreads();    // all warps: fill(kt) visible; compute(kt-1) done
            if (kt + 2 < KT) {
                int nbuf = buf + 2; if (nbuf >= 3) nbuf -= 3;
                fillA0(kt + 2, nbuf); fillB(kt + 2, nbuf);   // overwrites buf(kt-1)
                asm volatile("cp.async.commit_group;");
            }
            compute_stage(buf);
            if (++buf == 3) buf = 0;
        }
    }

    // Epilogue: bias + relu; store fp16 (intermediates) or fp32 (final)
    const int rbase = tile + warpM * 32 + (lane >> 2);
#pragma unroll
    for (int mf = 0; mf < 2; ++mf) {
        int r0 = rbase + mf * 16;
#pragma unroll
        for (int nf = 0; nf < 8; ++nf) {
            int col  = warpN * 64 + nf * 8 + (lane & 3) * 2;
            float b0 = __ldg(bias + col);
            float b1 = __ldg(bias + col + 1);
            float v0 = fmaxf(acc[mf][nf][0] + b0, 0.f);
            float v1 = fmaxf(acc[mf][nf][1] + b1, 0.f);
            float v2 = fmaxf(acc[mf][nf][2] + b0, 0.f);
            float v3 = fmaxf(acc[mf][nf][3] + b1, 0.f);
            if (HALF_OUT) {
                __half* Ch = (__half*)Cv;
                if (r0 < nrows)
                    *reinterpret_cast<__half2*>(Ch + (long)r0 * ldc + col) =
                        __floats2half2_rn(v0, v1);
                if (r0 + 8 < nrows)
                    *reinterpret_cast<__half2*>(Ch + (long)(r0 + 8) * ldc + col) =
                        __floats2half2_rn(v2, v3);
            } else {
                float* Cf = (float*)Cv;
                if (r0 < nrows)
                    *reinterpret_cast<float2*>(Cf + (long)r0 * ldc + col) =
                        make_float2(v0, v1);
                if (r0 + 8 < nrows)
                    *reinterpret_cast<float2*>(Cf + (long)(r0 + 8) * ldc + col) =
                        make_float2(v2, v3);
            }
        }
    }
}

// ---------------- kernels ----------------

__global__ void prep_kernel(const float* __restrict__ w10, const float* __restrict__ w1,
                            const float* __restrict__ w2, const float* __restrict__ wf) {
    int i      = blockIdx.x * blockDim.x + threadIdx.x;
    int stride = gridDim.x * blockDim.x;
    for (int j = i; j < 128 * 1280; j += stride) g_W1_0h[j] = __float2half_rn(w10[j]);
    for (int j = i; j < 6 * 128 * 512; j += stride) g_W1h[j] = __float2half_rn(w1[j]);
    for (int j = i; j < 6 * 128 * 256; j += stride) g_W2h[j] = __float2half_rn(w2[j]);
    for (int j = i; j < 256 * 768; j += stride) g_Wfh[j] = __float2half_rn(wf[j]);
}

__global__ void __launch_bounds__(256, 2)
l1_kernel(const float* __restrict__ update, const float* __restrict__ b1_0,
          const float* __restrict__ b1, int nrows) {
    int g = blockIdx.y;
    if (g == 0) {
        gemm16<1, true, 1280>(update, 4352, 0, 0, 1 << 20,
                              g_W1_0h, 1280, b1_0, g_out1h, 896, nrows);
    } else {
        gemm16<1, true, 512>(update, 4352, c_jA[g] * 256, c_jB[g] * 256, 256,
                             g_W1h + (g - 1) * 128 * 512, 512, b1 + (g - 1) * 128,
                             g_out1h + g * 128, 896, nrows);
    }
}

__global__ void __launch_bounds__(256, 2)
l2_kernel(const float* __restrict__ b2, int nrows) {
    int g = blockIdx.y;
    gemm16<0, true, 256>(g_out1h, 896, c_pA[g] * 128, c_pB[g] * 128, 128,
                         g_W2h + g * 128 * 256, 256, b2 + g * 128,
                         g_out2h + g * 128, 768, nrows);
}

__global__ void __launch_bounds__(256, 2)
l3_kernel(const float* __restrict__ bf, float* __restrict__ out, int nrows) {
    int y = blockIdx.y;   // output column half
    gemm16<0, false, 768>(g_out2h, 768, 0, 0, 1 << 20,
                          g_Wfh + y * 128 * 768, 768, bf + y * 128,
                          out + y * 128, 256, nrows);
}

// ---------------- launch ----------------

extern "C" void kernel_launch(void* const* d_in, const int* in_sizes, int n_in,
                              void* d_out, int out_size) {
    const float* update = (const float*)d_in[0];
    const float* W1_0   = (const float*)d_in[1];
    const float* b1_0   = (const float*)d_in[2];
    const float* W1     = (const float*)d_in[3];
    const float* b1     = (const float*)d_in[4];
    const float* W2     = (const float*)d_in[5];
    const float* b2     = (const float*)d_in[6];
    const float* Wf     = (const float*)d_in[7];
    const float* bf     = (const float*)d_in[8];

    int N  = in_sizes[0] / (17 * 256);
    int MT = (N + 127) / 128;

    cudaFuncSetAttribute(l1_kernel, cudaFuncAttributeMaxDynamicSharedMemorySize, SMEM_L1);
    cudaFuncSetAttribute(l2_kernel, cudaFuncAttributeMaxDynamicSharedMemorySize, SMEM_L23);
    cudaFuncSetAttribute(l3_kernel, cudaFuncAttributeMaxDynamicSharedMemorySize, SMEM_L23);

    prep_kernel<<<232, 256>>>(W1_0, W1, W2, Wf);
    l1_kernel<<<dim3(MT, 7), 256, SMEM_L1>>>(update, b1_0, b1, N);
    l2_kernel<<<dim3(MT, 6), 256, SMEM_L23>>>(b2, N);
    l3_kernel<<<dim3(MT, 2), 256, SMEM_L23>>>(bf, (float*)d_out, N);
}